// round 16
// baseline (speedup 1.0000x reference)
#include <cuda_runtime.h>
#include <cstdint>

typedef unsigned long long ULL;

// ---------------------------------------------------------------------------
// Problem constants: B=64, N=512, E=1, M=256, F=[1,8,8], K=[3,3], MLP=[512,128]
// ---------------------------------------------------------------------------
#define NODES 512
#define BATCH 64
#define MAXNZ 64   // max nonzeros per row supported (actual ~16, max ~35)
#define NSLOT 6    // wpair ring slots (4-deep prefetch + current + slack)

// ------------------------- device scratch (no allocs) -----------------------
static __device__ int   g_sp_cnt[NODES];
static __device__ short g_sp_cols[NODES * MAXNZ];
static __device__ int   g_s_cnt[NODES];
static __device__ short g_s_cols[NODES * MAXNZ];
static __device__ float g_s_vals[NODES * MAXNZ];

static __device__ float g_x0[NODES * BATCH];           // x transposed [n][b]
static __device__ float g_zs1a[NODES * BATCH];         // S x
static __device__ float g_zs1b[NODES * BATCH];         // S^2 x
static __device__ float g_x1[8 * NODES * BATCH];       // layer1 output [g][n][b]
static __device__ float g_zs2a[8 * NODES * BATCH];     // S x1
static __device__ float g_zs2b[8 * NODES * BATCH];     // S^2 x1
static __device__ float g_ypart[64 * NODES * BATCH];   // layer2 EV partials [fg][n][b]
static __device__ float g_y2[8 * NODES * BATCH];       // layer2 output = yf [i][b]
static __device__ float g_hpart[16 * 512 * BATCH];     // MLP1 splitK partials
static __device__ float g_h1[512 * BATCH];             // MLP1 hidden [j][b]

// ---------------------------------------------------------------------------
// 1) Build sparse structures from S + transpose x, in one kernel.
// ---------------------------------------------------------------------------
__global__ __launch_bounds__(512) void k_build(const float* __restrict__ S,
                                               const float* __restrict__ x) {
    if (blockIdx.x >= 32) {
        __shared__ float tile[32][33];
        int tt = blockIdx.x - 32;
        int mt = tt >> 1, bt = tt & 1;
        int tx = threadIdx.x & 31, ty0 = threadIdx.x >> 5;
#pragma unroll
        for (int p = 0; p < 2; p++) {
            int ty = ty0 + (p << 4);
            tile[ty][tx] = x[(bt * 32 + ty) * NODES + mt * 32 + tx];
        }
        __syncthreads();
#pragma unroll
        for (int p = 0; p < 2; p++) {
            int ty = ty0 + (p << 4);
            g_x0[(mt * 32 + ty) * BATCH + bt * 32 + tx] = tile[tx][ty];
        }
        return;
    }
    int m = blockIdx.x * 16 + (threadIdx.x >> 5);
    int lane = threadIdx.x & 31;
    unsigned lt = (1u << lane) - 1u;
    float v[16];
#pragma unroll
    for (int r = 0; r < 16; r++) v[r] = __ldg(S + (m << 9) + (r << 5) + lane);
    int sc = 0, spc = 0;
#pragma unroll
    for (int r = 0; r < 16; r++) {
        int n = (r << 5) + lane;
        bool nz = (v[r] != 0.0f);
        unsigned bs = __ballot_sync(0xffffffffu, nz);
        if (nz) {
            int idx = sc + __popc(bs & lt);
            if (idx < MAXNZ) { g_s_cols[m * MAXNZ + idx] = (short)n; g_s_vals[m * MAXNZ + idx] = v[r]; }
        }
        sc += __popc(bs);
        bool insp = ((fabsf(v[r]) > 1e-9f) || (n == m)) && !((m >= 256) && (n >= 256));
        unsigned bp = __ballot_sync(0xffffffffu, insp);
        if (insp) {
            int idx = spc + __popc(bp & lt);
            if (idx < MAXNZ) g_sp_cols[m * MAXNZ + idx] = (short)n;
        }
        spc += __popc(bp);
    }
    if (lane == 0) {
        g_s_cnt[m]  = sc  < MAXNZ ? sc  : MAXNZ;
        g_sp_cnt[m] = spc < MAXNZ ? spc : MAXNZ;
    }
}

// ---------------------------------------------------------------------------
// 2) Sparse S matvec (LSI powers), shuffle-broadcast form.
//    step 0: x0->zs1a | 1: zs1a->zs1b | 2: x1->zs2a | 3: zs2a->zs2b
// ---------------------------------------------------------------------------
__global__ __launch_bounds__(256) void k_spmv(int step, int nc) {
    const float* in; float* out;
    if (step == 0)      { in = g_x0;   out = g_zs1a; }
    else if (step == 1) { in = g_zs1a; out = g_zs1b; }
    else if (step == 2) { in = g_x1;   out = g_zs2a; }
    else                { in = g_zs2a; out = g_zs2b; }
    int gw = blockIdx.x * 8 + (threadIdx.x >> 5);
    int lane = threadIdx.x & 31;
    int c = gw >> 10;
    if (c >= nc) return;
    int m = (gw >> 1) & 511;
    int h = gw & 1;
    int cnt = g_s_cnt[m];
    float acc = 0.f;
    for (int jb = 0; jb < cnt; jb += 32) {
        int jn = cnt - jb; if (jn > 32) jn = 32;
        float sv = 0.f; int cv = 0;
        if (lane < jn) {
            cv = (int)g_s_cols[(m << 6) + jb + lane];
            sv = g_s_vals[(m << 6) + jb + lane];
        }
#pragma unroll 8
        for (int j = 0; j < jn; j++) {
            float wj = __shfl_sync(0xffffffffu, sv, j);
            int cj   = __shfl_sync(0xffffffffu, cv, j);
            acc += wj * __ldg(in + ((c << 9) + cj) * BATCH + (h << 5) + lane);
        }
    }
    out[((c << 9) + m) * BATCH + (h << 5) + lane] = acc;
}

// ---------------------------------------------------------------------------
// 3) Unified EV chain kernel v4 (both layers): half-warp per row, float2/lane.
//    (w, z-byte-offset) pairs staged in a 6-slot per-warp smem ring, prefetch
//    4 iterations ahead (4 x ~160cyc covers the ~577cyc scattered DRAM load).
//    Inner j: LDS.64 pair + IADD + LDS.64 z + 2 FFMA (no SHFL chains).
//    z ping-pong (2x64KB); y = z1+z2+z3 from the two buffers at k=2.
//    Layer1 fuses combine1 into the epilogue.
//    dyn smem: z 131072 + scoff 32768 + wpair 49152 = 212992.
// ---------------------------------------------------------------------------
__global__ __launch_bounds__(512, 1) void k_evchain(int layer,
                                                    const float* __restrict__ wEV,
                                                    const float* __restrict__ wLSI1,
                                                    const float* __restrict__ b1) {
    extern __shared__ char sraw[];
    float* zbuf0 = (float*)sraw;                               // [512][32]
    float* zbuf1 = (float*)(sraw + 65536);                     // [512][32]
    unsigned short* scoff = (unsigned short*)(sraw + 131072);  // [512][32] col<<7
    float2* wpair = (float2*)(sraw + 163840);                  // [16 warps][NSLOT][64]
    __shared__ int scnt[NODES];

    const int G = (layer == 1) ? 1 : 8;
    const float* xin = (layer == 1) ? g_x0 : g_x1;

    int h  = blockIdx.x & 1;
    int fg = blockIdx.x >> 1;
    int f  = (layer == 1) ? fg : (fg >> 3);
    int g  = (layer == 1) ? 0 : (fg & 7);
    int tid = threadIdx.x, w = tid >> 5, lane = tid & 31;
    int li = lane & 15, hb = lane & 16;    // half-lane index, half base (0/16)

    scnt[tid] = g_sp_cnt[tid];
    for (int idx = tid; idx < NODES * 32; idx += 512)
        scoff[idx] = (unsigned short)((int)g_sp_cols[((idx >> 5) << 6) + (idx & 31)] << 7);
    for (int idx = tid; idx < NODES * 32; idx += 512)
        zbuf0[idx] = xin[((g << 9) + (idx >> 5)) * BATCH + (h << 5) + (idx & 31)];
    __syncthreads();

    const int pbase = f * 3 * G + g;
    const char* wb = (const char*)wEV;

    // stage (w, off) pairs for row-iteration t into ring slot
    auto pf = [&](int t, int slot) {
        int kk = t >> 4, ii = t & 15;
        int myrow = (ii << 5) + hb + w;
        int cnt = scnt[myrow];
        unsigned wo = ((unsigned)(pbase + kk * G) << 20) + ((unsigned)myrow << 11);
        unsigned short o0 = scoff[(myrow << 5) + li];
        unsigned short o1 = scoff[(myrow << 5) + 16 + li];
        float wlo = (li < cnt)      ? __ldg((const float*)(wb + wo + ((unsigned)o0 >> 5))) : 0.f;
        float whi = (li + 16 < cnt) ? __ldg((const float*)(wb + wo + ((unsigned)o1 >> 5))) : 0.f;
        float2* wp = wpair + ((w * NSLOT + slot) << 6) + (hb << 1);
        wp[li]      = make_float2(wlo, __int_as_float((int)o0));
        wp[16 + li] = make_float2(whi, __int_as_float((int)o1));
    };

    pf(0, 0); pf(1, 1); pf(2, 2); pf(3, 3);
    __syncwarp();

    const float* zr = zbuf0;
    float* zw = zbuf1;
    int scur = 0, spre = 4;

    float wl0 = 0.f, wl1 = 0.f, wl2 = 0.f, bb = 0.f;
    if (layer == 1) { wl0 = wLSI1[f*3]; wl1 = wLSI1[f*3+1]; wl2 = wLSI1[f*3+2]; bb = b1[f]; }

    for (int t = 0; t < 48; t++) {
        if (t + 4 < 48) pf(t + 4, spre);
        __syncwarp();

        int kk = t >> 4, ii = t & 15;
        int myrow = (ii << 5) + hb + w;
        int rA = (ii << 5) + w;
        int cA = scnt[rA], cB = scnt[rA + 16];
        int jmax = cA > cB ? cA : cB;
        int jm = jmax < 32 ? jmax : 32;

        const float2* wp = wpair + ((w * NSLOT + scur) << 6) + (hb << 1);
        const char* zb = (const char*)zr + (li << 3);
        float ax = 0.f, ay = 0.f;
#pragma unroll 4
        for (int j = 0; j < jm; j++) {
            float2 p = wp[j];
            float2 zv = *(const float2*)(zb + __float_as_int(p.y));
            ax += p.x * zv.x; ay += p.x * zv.y;
        }
        if (jmax > 32) {   // rare tail (cnt up to 64 via global lists)
            int cmy = scnt[myrow];
            int rem = cmy - 32;
            int cv = 0; float wt = 0.f;
            if (rem > 0 && li < rem) {
                cv = (int)g_sp_cols[(myrow << 6) + 32 + li];
                wt = __ldg((const float*)(wb + (((unsigned)(pbase + kk * G) << 20)
                                               + ((unsigned)myrow << 11) + ((unsigned)cv << 2))));
            }
            int remMax = jmax - 32;
            for (int j = 0; j < remMax; j++) {
                float wj = __shfl_sync(0xffffffffu, wt, hb + j);
                int cj  = __shfl_sync(0xffffffffu, cv, hb + j);
                float2 zv = *(const float2*)((const char*)zr + (cj << 7) + (li << 3));
                ax += wj * zv.x; ay += wj * zv.y;
            }
        }

        if (kk < 2) {
            *(float2*)((char*)zw + (myrow << 7) + (li << 3)) = make_float2(ax, ay);
            if (ii == 15) {
                __syncthreads();
                const float* tz = zr; zr = zw; zw = (float*)tz;
            }
        } else {
            // zr = z2 (buf), zw = z1 (buf): y = z3(=acc) + z1 + z2
            float2 z1 = *(const float2*)((const char*)zw + (myrow << 7) + (li << 3));
            float2 z2 = *(const float2*)((const char*)zr + (myrow << 7) + (li << 3));
            float yx = ax + z1.x + z2.x;
            float yy = ay + z1.y + z2.y;
            int off = (myrow << 6) + (h << 5) + (li << 1);
            if (layer == 1) {
                float2 v0 = *(const float2*)&g_x0[off];
                float2 v1 = *(const float2*)&g_zs1a[off];
                float2 v2 = *(const float2*)&g_zs1b[off];
                yx += wl0 * v0.x + wl1 * v1.x + wl2 * v2.x + bb;
                yy += wl0 * v0.y + wl1 * v1.y + wl2 * v2.y + bb;
                *(float2*)&g_x1[(f << 15) + off] = make_float2(yx, yy);
            } else {
                *(float2*)&g_ypart[((size_t)fg << 15) + off] = make_float2(yx, yy);
            }
        }
        scur++; if (scur == NSLOT) scur = 0;
        spre++; if (spre == NSLOT) spre = 0;
    }
}

// ---------------------------------------------------------------------------
// 4) Combine layer2: y2 = sum_g ypart + sum_{k,g} wLSI2[f,k,g] * S^k x1 + b2[f]
// ---------------------------------------------------------------------------
__global__ void k_combine2(const float* __restrict__ wLSI2, const float* __restrict__ b2) {
    int idx = blockIdx.x * blockDim.x + threadIdx.x;   // 8*512*64
    int f = idx >> 15; int mb = idx & 32767;
    float acc = b2[f];
#pragma unroll
    for (int g = 0; g < 8; g++) {
        acc += g_ypart[(((f << 3) + g) << 15) + mb];
        acc += wLSI2[f * 24 + g]      * g_x1[(g << 15) + mb];
        acc += wLSI2[f * 24 + 8 + g]  * g_zs2a[(g << 15) + mb];
        acc += wLSI2[f * 24 + 16 + g] * g_zs2b[(g << 15) + mb];
    }
    g_y2[idx] = acc;
}

// ---------------------------------------------------------------------------
// 5) MLP layer 1: h[j][b] = sum_i W1[j][i] * yf[i][b]  (splitK, f32x2 packed)
// ---------------------------------------------------------------------------
__device__ __forceinline__ ULL ffma2(ULL a, ULL b, ULL c) {
    ULL d; asm("fma.rn.f32x2 %0, %1, %2, %3;" : "=l"(d) : "l"(a), "l"(b), "l"(c));
    return d;
}
__device__ __forceinline__ ULL packdup(float x) {
    ULL r; asm("mov.b64 %0, {%1, %1};" : "=l"(r) : "f"(x));
    return r;
}

__global__ __launch_bounds__(256) void k_mlp1(const float* __restrict__ W1) {
    __shared__ ULL sW[64 * 32];
    __shared__ __align__(16) float sX[32 * 64];
    int jt = blockIdx.x;      // 0..7
    int kt = blockIdx.y;      // 0..15
    int tid = threadIdx.x;
    int bp = tid & 31;
    int jg = tid >> 5;
    ULL acc[8];
#pragma unroll
    for (int jj = 0; jj < 8; jj++) acc[jj] = 0ull;

    for (int ic = 0; ic < 8; ic++) {
        int i0 = kt * 256 + ic * 32;
        {
            int ii = tid & 31; int jr0 = tid >> 5;
#pragma unroll
            for (int q = 0; q < 8; q++) {
                int jr = jr0 + (q << 3);
                sW[(jr << 5) + ii] = packdup(W1[(size_t)(jt * 64 + jr) * 4096 + i0 + ii]);
            }
            int b = tid & 63; int ii0 = tid >> 6;
#pragma unroll
            for (int q = 0; q < 8; q++) {
                int ii2 = ii0 + (q << 2);
                sX[(ii2 << 6) + b] = g_y2[(size_t)(i0 + ii2) * BATCH + b];
            }
        }
        __syncthreads();
#pragma unroll
        for (int ii = 0; ii < 32; ii++) {
            ULL xv = *reinterpret_cast<const ULL*>(&sX[(ii << 6) + (bp << 1)]);
#pragma unroll
            for (int jj = 0; jj < 8; jj++)
                acc[jj] = ffma2(sW[(((jg << 3) + jj) << 5) + ii], xv, acc[jj]);
        }
        __syncthreads();
    }
#pragma unroll
    for (int jj = 0; jj < 8; jj++) {
        int j = jt * 64 + (jg << 3) + jj;
        *reinterpret_cast<ULL*>(&g_hpart[((kt << 9) + j) * BATCH + (bp << 1)]) = acc[jj];
    }
}

__global__ void k_hreduce(const float* __restrict__ bW1) {
    int idx = blockIdx.x * blockDim.x + threadIdx.x;   // 512*64
    float s = bW1[idx >> 6];
#pragma unroll
    for (int kt = 0; kt < 16; kt++) s += g_hpart[(kt << 15) + idx];
    g_h1[idx] = s;
}

// ---------------------------------------------------------------------------
// 6) MLP layer 2: out[b][j2] = sum_j W2[j2][j] * h[j][b] + bW2[j2]
// ---------------------------------------------------------------------------
__global__ void k_mlp2(const float* __restrict__ W2, const float* __restrict__ bW2,
                       float* __restrict__ out) {
    int j2 = blockIdx.x; int b = threadIdx.x;
    float acc = 0.f;
#pragma unroll 8
    for (int j = 0; j < 512; j++)
        acc += W2[j2 * 512 + j] * g_h1[(j << 6) + b];
    out[b * 128 + j2] = acc + bW2[j2];
}

// ---------------------------------------------------------------------------
// launch
// ---------------------------------------------------------------------------
extern "C" void kernel_launch(void* const* d_in, const int* in_sizes, int n_in,
                              void* d_out, int out_size) {
    const float* x     = (const float*)d_in[0];
    const float* S     = (const float*)d_in[1];
    const float* wEV1  = (const float*)d_in[2];
    const float* wLSI1 = (const float*)d_in[3];
    const float* b1    = (const float*)d_in[4];
    const float* wEV2  = (const float*)d_in[5];
    const float* wLSI2 = (const float*)d_in[6];
    const float* b2    = (const float*)d_in[7];
    const float* W1    = (const float*)d_in[8];
    const float* bW1   = (const float*)d_in[9];
    const float* W2    = (const float*)d_in[10];
    const float* bW2   = (const float*)d_in[11];
    float* out = (float*)d_out;

    const int EVSMEM = 163840 + 16 * NSLOT * 64 * 8;   // 212992
    cudaFuncSetAttribute(k_evchain, cudaFuncAttributeMaxDynamicSharedMemorySize, EVSMEM);

    k_build<<<64, 512>>>(S, x);                         // build + transpose
    k_spmv<<<128, 256>>>(0, 1);                         // S x
    k_spmv<<<128, 256>>>(1, 1);                         // S^2 x
    k_evchain<<<16, 512, EVSMEM>>>(1, wEV1, wLSI1, b1); // layer1 EV + combine1
    k_spmv<<<1024, 256>>>(2, 8);                        // S x1
    k_spmv<<<1024, 256>>>(3, 8);                        // S^2 x1
    k_evchain<<<128, 512, EVSMEM>>>(2, wEV2, wLSI1, b1);// layer2 EV -> ypart
    k_combine2<<<1024, 256>>>(wLSI2, b2);
    dim3 gm1(8, 16);
    k_mlp1<<<gm1, 256>>>(W1);
    k_hreduce<<<512, 64>>>(bW1);
    k_mlp2<<<128, 64>>>(W2, bW2, out);
}

// round 17
// speedup vs baseline: 1.6300x; 1.6300x over previous
#include <cuda_runtime.h>
#include <cstdint>

typedef unsigned long long ULL;

// ---------------------------------------------------------------------------
// Problem constants: B=64, N=512, E=1, M=256, F=[1,8,8], K=[3,3], MLP=[512,128]
// ---------------------------------------------------------------------------
#define NODES 512
#define BATCH 64
#define MAXNZ 64   // max nonzeros per row supported (actual ~16, max ~35)

// ------------------------- device scratch (no allocs) -----------------------
static __device__ int   g_sp_cnt[NODES];
static __device__ short g_sp_cols[NODES * MAXNZ];
static __device__ int   g_s_cnt[NODES];
static __device__ short g_s_cols[NODES * MAXNZ];
static __device__ float g_s_vals[NODES * MAXNZ];

static __device__ float g_x0[NODES * BATCH];           // x transposed [n][b]
static __device__ float g_zs1a[NODES * BATCH];         // S x
static __device__ float g_zs1b[NODES * BATCH];         // S^2 x
static __device__ float g_ezA[8 * NODES * BATCH];      // layer1 z1 [f][n][b]
static __device__ float g_ezB[8 * NODES * BATCH];      // layer1 z2 [f][n][b]
static __device__ float g_x1[8 * NODES * BATCH];       // layer1 output [g][n][b]
static __device__ float g_zs2a[8 * NODES * BATCH];     // S x1
static __device__ float g_zs2b[8 * NODES * BATCH];     // S^2 x1
static __device__ float g_e2A[64 * NODES * BATCH];     // layer2 z1 [u][n][b]  (8MB)
static __device__ float g_e2B[64 * NODES * BATCH];     // layer2 z2 [u][n][b]  (8MB)
static __device__ float g_ypart[64 * NODES * BATCH];   // layer2 EV y [u][n][b]
static __device__ float g_y2[8 * NODES * BATCH];       // layer2 output = yf [i][b]
static __device__ float g_hpart[16 * 512 * BATCH];     // MLP1 splitK partials
static __device__ float g_h1[512 * BATCH];             // MLP1 hidden [j][b]

// ---------------------------------------------------------------------------
// 1) Build sparse structures from S + transpose x, in one kernel.
// ---------------------------------------------------------------------------
__global__ __launch_bounds__(512) void k_build(const float* __restrict__ S,
                                               const float* __restrict__ x) {
    if (blockIdx.x >= 32) {
        __shared__ float tile[32][33];
        int tt = blockIdx.x - 32;
        int mt = tt >> 1, bt = tt & 1;
        int tx = threadIdx.x & 31, ty0 = threadIdx.x >> 5;
#pragma unroll
        for (int p = 0; p < 2; p++) {
            int ty = ty0 + (p << 4);
            tile[ty][tx] = x[(bt * 32 + ty) * NODES + mt * 32 + tx];
        }
        __syncthreads();
#pragma unroll
        for (int p = 0; p < 2; p++) {
            int ty = ty0 + (p << 4);
            g_x0[(mt * 32 + ty) * BATCH + bt * 32 + tx] = tile[tx][ty];
        }
        return;
    }
    int m = blockIdx.x * 16 + (threadIdx.x >> 5);
    int lane = threadIdx.x & 31;
    unsigned lt = (1u << lane) - 1u;
    float v[16];
#pragma unroll
    for (int r = 0; r < 16; r++) v[r] = __ldg(S + (m << 9) + (r << 5) + lane);
    int sc = 0, spc = 0;
#pragma unroll
    for (int r = 0; r < 16; r++) {
        int n = (r << 5) + lane;
        bool nz = (v[r] != 0.0f);
        unsigned bs = __ballot_sync(0xffffffffu, nz);
        if (nz) {
            int idx = sc + __popc(bs & lt);
            if (idx < MAXNZ) { g_s_cols[m * MAXNZ + idx] = (short)n; g_s_vals[m * MAXNZ + idx] = v[r]; }
        }
        sc += __popc(bs);
        bool insp = ((fabsf(v[r]) > 1e-9f) || (n == m)) && !((m >= 256) && (n >= 256));
        unsigned bp = __ballot_sync(0xffffffffu, insp);
        if (insp) {
            int idx = spc + __popc(bp & lt);
            if (idx < MAXNZ) g_sp_cols[m * MAXNZ + idx] = (short)n;
        }
        spc += __popc(bp);
    }
    if (lane == 0) {
        g_s_cnt[m]  = sc  < MAXNZ ? sc  : MAXNZ;
        g_sp_cnt[m] = spc < MAXNZ ? spc : MAXNZ;
    }
}

// ---------------------------------------------------------------------------
// 2) Layer-1 EV as 3 global-z steps (full-chip parallel, z L2-resident).
//    Warp = (fp, row): fp 0..7 = EV chains, fp 8 = LSI S-power matvec.
//    k=0: z1 = Phi0 x  ; zs1a = S x
//    k=1: z2 = Phi1 z1 ; zs1b = S zs1a
//    k=2: z3 = Phi2 z2, then x1 = z1+z2+z3 + sum_k wLSI1[f,k] S^k x + b1[f]
// ---------------------------------------------------------------------------
__global__ __launch_bounds__(256) void k_ev1(int k, const float* __restrict__ wEV1,
                                             const float* __restrict__ wLSI1,
                                             const float* __restrict__ b1) {
    int gw = blockIdx.x * 8 + (threadIdx.x >> 5);
    int lane = threadIdx.x & 31;
    int fp = gw >> 9;          // 0..8
    int m  = gw & 511;

    const float* zin; float* zout;
    int cnt;
    if (fp == 8) {
        if (k == 2) return;
        cnt  = g_s_cnt[m];
        zin  = (k == 0) ? g_x0 : g_zs1a;
        zout = (k == 0) ? g_zs1a : g_zs1b;
    } else {
        cnt  = g_sp_cnt[m];
        zin  = (k == 0) ? g_x0 : ((k == 1) ? g_ezA + (fp << 15) : g_ezB + (fp << 15));
        zout = (k == 0) ? g_ezA + (fp << 15) : ((k == 1) ? g_ezB + (fp << 15) : 0);
    }
    const float* wpl = (fp < 8) ? (wEV1 + ((size_t)(fp * 3 + k) << 18)) : 0;

    float ax = 0.f, ay = 0.f;
    for (int jb = 0; jb < cnt; jb += 32) {
        int jn = cnt - jb; if (jn > 32) jn = 32;
        int cv = 0; float wv = 0.f;
        if (lane < jn) {
            if (fp == 8) {
                cv = (int)g_s_cols[(m << 6) + jb + lane];
                wv = g_s_vals[(m << 6) + jb + lane];
            } else {
                cv = (int)g_sp_cols[(m << 6) + jb + lane];
                wv = __ldg(wpl + (m << 9) + cv);
            }
        }
#pragma unroll 8
        for (int j = 0; j < jn; j++) {
            float wj = __shfl_sync(0xffffffffu, wv, j);
            int   cj = __shfl_sync(0xffffffffu, cv, j);
            float2 zv = *(const float2*)&zin[(cj << 6) + (lane << 1)];
            ax += wj * zv.x; ay += wj * zv.y;
        }
    }

    int off = (m << 6) + (lane << 1);
    if (fp == 8 || k < 2) {
        *(float2*)&zout[off] = make_float2(ax, ay);
    } else {
        // fused combine1
        float2 z1 = *(const float2*)&g_ezA[(fp << 15) + off];
        float2 z2 = *(const float2*)&g_ezB[(fp << 15) + off];
        float2 v0 = *(const float2*)&g_x0[off];
        float2 v1 = *(const float2*)&g_zs1a[off];
        float2 v2 = *(const float2*)&g_zs1b[off];
        float wl0 = wLSI1[fp * 3], wl1 = wLSI1[fp * 3 + 1], wl2 = wLSI1[fp * 3 + 2];
        float bb = b1[fp];
        float yx = ax + z1.x + z2.x + wl0 * v0.x + wl1 * v1.x + wl2 * v2.x + bb;
        float yy = ay + z1.y + z2.y + wl0 * v0.y + wl1 * v1.y + wl2 * v2.y + bb;
        *(float2*)&g_x1[(fp << 15) + off] = make_float2(yx, yy);
    }
}

// ---------------------------------------------------------------------------
// 3) Layer-2 EV as 3 global-z steps. Unit u: 0..63 = EV chain (f=u>>3, g=u&7),
//    u=64..71 = LSI S-power matvec channel (g = u-64) riding along.
//    k=0: z1[u] = Phi_{f,0,g} x1[g]   ; zs2a = S x1
//    k=1: z2[u] = Phi_{f,1,g} z1[u]   ; zs2b = S zs2a
//    k=2: ypart[u] = Phi_{f,2,g} z2[u] + z1[u] + z2[u]
//    z buffers are 8MB each -> L2-resident; 36864 warps hide L2 latency.
// ---------------------------------------------------------------------------
__global__ __launch_bounds__(256) void k_ev2(int k, const float* __restrict__ wEV2) {
    int gw = blockIdx.x * 8 + (threadIdx.x >> 5);
    int lane = threadIdx.x & 31;
    int u = gw >> 9;           // 0..71
    int m = gw & 511;

    const float* zin; float* zout = 0;
    int cnt;
    const float* wpl = 0;
    if (u >= 64) {
        if (k == 2) return;
        cnt = g_s_cnt[m];
        size_t co = (size_t)(u - 64) << 15;
        zin  = (k == 0) ? (g_x1 + co) : (g_zs2a + co);
        zout = (k == 0) ? (g_zs2a + co) : (g_zs2b + co);
    } else {
        cnt = g_sp_cnt[m];
        int plane = ((u >> 3) * 3 + k) * 8 + (u & 7);
        wpl = wEV2 + ((size_t)plane << 18);
        size_t uo = (size_t)u << 15;
        zin  = (k == 0) ? (g_x1 + ((size_t)(u & 7) << 15))
             : ((k == 1) ? (g_e2A + uo) : (g_e2B + uo));
        zout = (k == 0) ? (g_e2A + uo) : ((k == 1) ? (g_e2B + uo) : 0);
    }

    float ax = 0.f, ay = 0.f;
    for (int jb = 0; jb < cnt; jb += 32) {
        int jn = cnt - jb; if (jn > 32) jn = 32;
        int cv = 0; float wv = 0.f;
        if (lane < jn) {
            if (u >= 64) {
                cv = (int)g_s_cols[(m << 6) + jb + lane];
                wv = g_s_vals[(m << 6) + jb + lane];
            } else {
                cv = (int)g_sp_cols[(m << 6) + jb + lane];
                wv = __ldg(wpl + (m << 9) + cv);
            }
        }
#pragma unroll 8
        for (int j = 0; j < jn; j++) {
            float wj = __shfl_sync(0xffffffffu, wv, j);
            int   cj = __shfl_sync(0xffffffffu, cv, j);
            float2 zv = *(const float2*)&zin[(cj << 6) + (lane << 1)];
            ax += wj * zv.x; ay += wj * zv.y;
        }
    }

    int off = (m << 6) + (lane << 1);
    if (u >= 64 || k < 2) {
        *(float2*)&zout[off] = make_float2(ax, ay);
    } else {
        size_t uo = (size_t)u << 15;
        float2 z1 = *(const float2*)&g_e2A[uo + off];
        float2 z2 = *(const float2*)&g_e2B[uo + off];
        *(float2*)&g_ypart[uo + off] = make_float2(ax + z1.x + z2.x, ay + z1.y + z2.y);
    }
}

// ---------------------------------------------------------------------------
// 4) Combine layer2: y2 = sum_g ypart + sum_{k,g} wLSI2[f,k,g] * S^k x1 + b2[f]
// ---------------------------------------------------------------------------
__global__ void k_combine2(const float* __restrict__ wLSI2, const float* __restrict__ b2) {
    int idx = blockIdx.x * blockDim.x + threadIdx.x;   // 8*512*64
    int f = idx >> 15; int mb = idx & 32767;
    float acc = b2[f];
#pragma unroll
    for (int g = 0; g < 8; g++) {
        acc += g_ypart[(((f << 3) + g) << 15) + mb];
        acc += wLSI2[f * 24 + g]      * g_x1[(g << 15) + mb];
        acc += wLSI2[f * 24 + 8 + g]  * g_zs2a[(g << 15) + mb];
        acc += wLSI2[f * 24 + 16 + g] * g_zs2b[(g << 15) + mb];
    }
    g_y2[idx] = acc;
}

// ---------------------------------------------------------------------------
// 5) MLP layer 1: h[j][b] = sum_i W1[j][i] * yf[i][b]  (splitK, f32x2 packed)
// ---------------------------------------------------------------------------
__device__ __forceinline__ ULL ffma2(ULL a, ULL b, ULL c) {
    ULL d; asm("fma.rn.f32x2 %0, %1, %2, %3;" : "=l"(d) : "l"(a), "l"(b), "l"(c));
    return d;
}
__device__ __forceinline__ ULL packdup(float x) {
    ULL r; asm("mov.b64 %0, {%1, %1};" : "=l"(r) : "f"(x));
    return r;
}

__global__ __launch_bounds__(256) void k_mlp1(const float* __restrict__ W1) {
    __shared__ ULL sW[64 * 32];
    __shared__ __align__(16) float sX[32 * 64];
    int jt = blockIdx.x;      // 0..7
    int kt = blockIdx.y;      // 0..15
    int tid = threadIdx.x;
    int bp = tid & 31;
    int jg = tid >> 5;
    ULL acc[8];
#pragma unroll
    for (int jj = 0; jj < 8; jj++) acc[jj] = 0ull;

    for (int ic = 0; ic < 8; ic++) {
        int i0 = kt * 256 + ic * 32;
        {
            int ii = tid & 31; int jr0 = tid >> 5;
#pragma unroll
            for (int q = 0; q < 8; q++) {
                int jr = jr0 + (q << 3);
                sW[(jr << 5) + ii] = packdup(W1[(size_t)(jt * 64 + jr) * 4096 + i0 + ii]);
            }
            int b = tid & 63; int ii0 = tid >> 6;
#pragma unroll
            for (int q = 0; q < 8; q++) {
                int ii2 = ii0 + (q << 2);
                sX[(ii2 << 6) + b] = g_y2[(size_t)(i0 + ii2) * BATCH + b];
            }
        }
        __syncthreads();
#pragma unroll
        for (int ii = 0; ii < 32; ii++) {
            ULL xv = *reinterpret_cast<const ULL*>(&sX[(ii << 6) + (bp << 1)]);
#pragma unroll
            for (int jj = 0; jj < 8; jj++)
                acc[jj] = ffma2(sW[(((jg << 3) + jj) << 5) + ii], xv, acc[jj]);
        }
        __syncthreads();
    }
#pragma unroll
    for (int jj = 0; jj < 8; jj++) {
        int j = jt * 64 + (jg << 3) + jj;
        *reinterpret_cast<ULL*>(&g_hpart[((kt << 9) + j) * BATCH + (bp << 1)]) = acc[jj];
    }
}

__global__ void k_hreduce(const float* __restrict__ bW1) {
    int idx = blockIdx.x * blockDim.x + threadIdx.x;   // 512*64
    float s = bW1[idx >> 6];
#pragma unroll
    for (int kt = 0; kt < 16; kt++) s += g_hpart[(kt << 15) + idx];
    g_h1[idx] = s;
}

// ---------------------------------------------------------------------------
// 6) MLP layer 2: out[b][j2] = sum_j W2[j2][j] * h[j][b] + bW2[j2]
// ---------------------------------------------------------------------------
__global__ void k_mlp2(const float* __restrict__ W2, const float* __restrict__ bW2,
                       float* __restrict__ out) {
    int j2 = blockIdx.x; int b = threadIdx.x;
    float acc = 0.f;
#pragma unroll 8
    for (int j = 0; j < 512; j++)
        acc += W2[j2 * 512 + j] * g_h1[(j << 6) + b];
    out[b * 128 + j2] = acc + bW2[j2];
}

// ---------------------------------------------------------------------------
// launch
// ---------------------------------------------------------------------------
extern "C" void kernel_launch(void* const* d_in, const int* in_sizes, int n_in,
                              void* d_out, int out_size) {
    const float* x     = (const float*)d_in[0];
    const float* S     = (const float*)d_in[1];
    const float* wEV1  = (const float*)d_in[2];
    const float* wLSI1 = (const float*)d_in[3];
    const float* b1    = (const float*)d_in[4];
    const float* wEV2  = (const float*)d_in[5];
    const float* wLSI2 = (const float*)d_in[6];
    const float* b2    = (const float*)d_in[7];
    const float* W1    = (const float*)d_in[8];
    const float* bW1   = (const float*)d_in[9];
    const float* W2    = (const float*)d_in[10];
    const float* bW2   = (const float*)d_in[11];
    float* out = (float*)d_out;

    k_build<<<64, 512>>>(S, x);                  // build + transpose
    k_ev1<<<576, 256>>>(0, wEV1, wLSI1, b1);     // z1 = Phi0 x ; zs1a = S x
    k_ev1<<<576, 256>>>(1, wEV1, wLSI1, b1);     // z2 = Phi1 z1 ; zs1b = S^2 x
    k_ev1<<<576, 256>>>(2, wEV1, wLSI1, b1);     // z3 + combine1 -> x1
    k_ev2<<<4608, 256>>>(0, wEV2);               // z1[u] ; zs2a = S x1
    k_ev2<<<4608, 256>>>(1, wEV2);               // z2[u] ; zs2b = S^2 x1
    k_ev2<<<4608, 256>>>(2, wEV2);               // ypart[u] = z1+z2+z3
    k_combine2<<<1024, 256>>>(wLSI2, b2);
    dim3 gm1(8, 16);
    k_mlp1<<<gm1, 256>>>(W1);
    k_hreduce<<<512, 64>>>(bW1);
    k_mlp2<<<128, 64>>>(W2, bW2, out);
}